// round 1
// baseline (speedup 1.0000x reference)
#include <cuda_runtime.h>
#include <cuda_bf16.h>
#include <math.h>

// Problem constants
#define B_    1024
#define T_    70
#define E_    300     // input dim per layer (= 2H)
#define H_    150
#define G_    600     // 4H gate width
#define DEPTH_ 5
#define M_    (B_ * T_)   // 71680 rows for the big input GEMM

// ---------------- scratch (static device memory; no allocation) ----------------
__device__ float g_zx_f[M_ * G_];   // forward  input pre-activations  [B*T, 600]
__device__ float g_zx_b[M_ * G_];   // backward input pre-activations  [B*T, 600]
__device__ float g_buf0[M_ * E_];   // layer ping buffer [B,T,300]
__device__ float g_buf1[M_ * E_];   // layer pong buffer
__device__ int   g_lens[B_];

// ---------------- helpers ----------------
__device__ __forceinline__ float sigf(float x) {
    return __fdividef(1.f, 1.f + __expf(-x));
}
__device__ __forceinline__ float tanhf_fast(float x) {
    // tanh(x) = 2*sigmoid(2x) - 1 ; saturates correctly for large |x|
    return __fdividef(2.f, 1.f + __expf(-2.f * x)) - 1.f;
}

// ---------------- lens = sum(mask) per batch row ----------------
__global__ void lens_kernel(const int* __restrict__ mask) {
    int b = blockIdx.x * blockDim.x + threadIdx.x;
    if (b < B_) {
        int s = 0;
        #pragma unroll
        for (int t = 0; t < T_; t++) s += mask[b * T_ + t];
        g_lens[b] = s;
    }
}

// ---------------- SGEMM: C[M,600] = A[M,300] @ Wk[300,600] + bias ----------------
// Tiles: BM=128, BN=64, BK=16; 256 threads; 8x4 per-thread tile.
__global__ __launch_bounds__(256) void sgemm_bias(
    const float* __restrict__ A, const float* __restrict__ Wk,
    const float* __restrict__ bias, float* __restrict__ C) {
    __shared__ float As[16][132];   // As[k][m], padded
    __shared__ float Ws[16][68];    // Ws[k][n], padded

    const int tid = threadIdx.x;
    const int m0 = blockIdx.x * 128;
    const int n0 = blockIdx.y * 64;
    const int tx = tid & 15;        // 4-col group
    const int ty = tid >> 4;        // 8-row group

    float acc[8][4];
    #pragma unroll
    for (int i = 0; i < 8; i++)
        #pragma unroll
        for (int j = 0; j < 4; j++) acc[i][j] = 0.f;

    for (int k0 = 0; k0 < 300; k0 += 16) {
        // load A tile (128x16) as 512 float4s, 2 per thread, store transposed
        #pragma unroll
        for (int l = 0; l < 2; l++) {
            int q   = tid + l * 256;
            int row = q >> 2;
            int kq  = (q & 3) * 4;
            float4 v = make_float4(0.f, 0.f, 0.f, 0.f);
            if (k0 + kq < 300)      // K=300 is a multiple of 4: quad all-or-none
                v = *(const float4*)(A + (m0 + row) * 300 + k0 + kq);
            As[kq + 0][row] = v.x;
            As[kq + 1][row] = v.y;
            As[kq + 2][row] = v.z;
            As[kq + 3][row] = v.w;
        }
        // load W tile (16x64) as 256 float4s, 1 per thread
        {
            int kk = tid >> 4;
            int nq = (tid & 15) * 4;
            int gn = n0 + nq;
            float4 v = make_float4(0.f, 0.f, 0.f, 0.f);
            if ((k0 + kk) < 300 && gn < 600)   // N=600 mult of 4: all-or-none
                v = *(const float4*)(Wk + (k0 + kk) * 600 + gn);
            *(float4*)&Ws[kk][nq] = v;
        }
        __syncthreads();

        #pragma unroll
        for (int kk = 0; kk < 16; kk++) {
            float4 a0 = *(const float4*)&As[kk][ty * 8];
            float4 a1 = *(const float4*)&As[kk][ty * 8 + 4];
            float4 w  = *(const float4*)&Ws[kk][tx * 4];
            float ar[8] = {a0.x, a0.y, a0.z, a0.w, a1.x, a1.y, a1.z, a1.w};
            float wr[4] = {w.x, w.y, w.z, w.w};
            #pragma unroll
            for (int i = 0; i < 8; i++)
                #pragma unroll
                for (int j = 0; j < 4; j++)
                    acc[i][j] += ar[i] * wr[j];
        }
        __syncthreads();
    }

    int gn = n0 + tx * 4;
    if (gn < 600) {
        float4 bv = *(const float4*)(bias + gn);
        #pragma unroll
        for (int i = 0; i < 8; i++) {
            int gm = m0 + ty * 8 + i;
            float4 o = make_float4(acc[i][0] + bv.x, acc[i][1] + bv.y,
                                   acc[i][2] + bv.z, acc[i][3] + bv.w);
            *(float4*)(C + gm * 600 + gn) = o;
        }
    }
}

// ---------------- recurrent layer (fw + bw in one grid) ----------------
// Block: 16 batch rows, 608 threads. Persistent over all 70 timesteps.
// Phase 1: z[16,600] = Zx[b,t] + h[16,150] @ Wh[150,600] (Wh streamed from L2)
// Phase 2: gates -> c,h update; h kept in SMEM (hT[k][r] layout), c in registers.
// Backward direction scans t = len-1-s per row; inactive steps write zeros at t=s.
__global__ __launch_bounds__(608) void lstm_layer(
    const float* __restrict__ zx_f, const float* __restrict__ zx_b,
    const float* __restrict__ wh_f, const float* __restrict__ wh_b,
    float* __restrict__ out) {
    __shared__ float hT[150][16];     // hT[k][r]
    __shared__ float zs[16][600];     // z staging
    __shared__ int   lens_s[16];

    const int tid = threadIdx.x;
    const int dir = blockIdx.y;
    const int b0  = blockIdx.x * 16;
    const float* zx = dir ? zx_b : zx_f;
    const float* Wh = dir ? wh_b : wh_f;

    if (tid < 16) lens_s[tid] = g_lens[b0 + tid];
    for (int i = tid; i < 150 * 16; i += 608) ((float*)hT)[i] = 0.f;

    // phase-1 mapping: 600 threads = 150 col-groups x 4 row-groups (4 cols x 4 rows each)
    const int cg  = (tid < 600) ? (tid % 150) : 0;
    const int rg1 = (tid < 600) ? (tid / 150) : 0;
    // phase-2 mapping: 600 threads = hidden j (0..149) x 4 row-groups
    const int j   = tid % 150;
    const int rg2 = tid / 150;

    float c[4] = {0.f, 0.f, 0.f, 0.f};
    __syncthreads();

    for (int s = 0; s < T_; s++) {
        // ---- phase 1: GEMM ----
        if (tid < 600) {
            float a[4][4];
            #pragma unroll
            for (int i = 0; i < 4; i++) {
                int r   = rg1 * 4 + i;
                int b   = b0 + r;
                int len = lens_s[r];
                bool act = (s < len);
                int t = act ? (dir ? (len - 1 - s) : s) : 0;
                float4 z4 = *(const float4*)(zx + (b * 70 + t) * 600 + cg * 4);
                a[i][0] = z4.x; a[i][1] = z4.y; a[i][2] = z4.z; a[i][3] = z4.w;
            }
            const float*  wp = Wh + cg * 4;
            const float4* hp = ((const float4*)hT) + rg1;   // hT row = 4 float4s
            #pragma unroll 5
            for (int k = 0; k < 150; k++) {
                float4 w = *(const float4*)(wp + k * 600);
                float4 h = hp[k * 4];
                float hh[4] = {h.x, h.y, h.z, h.w};
                float ww[4] = {w.x, w.y, w.z, w.w};
                #pragma unroll
                for (int i = 0; i < 4; i++)
                    #pragma unroll
                    for (int q = 0; q < 4; q++)
                        a[i][q] += hh[i] * ww[q];
            }
            #pragma unroll
            for (int i = 0; i < 4; i++)
                *(float4*)&zs[rg1 * 4 + i][cg * 4] =
                    make_float4(a[i][0], a[i][1], a[i][2], a[i][3]);
        }
        __syncthreads();

        // ---- phase 2: gates + state update ----
        if (tid < 600) {
            float4 hold = *(float4*)&hT[j][rg2 * 4];
            float hv[4] = {hold.x, hold.y, hold.z, hold.w};
            #pragma unroll
            for (int i = 0; i < 4; i++) {
                int r   = rg2 * 4 + i;
                int b   = b0 + r;
                int len = lens_s[r];
                bool act = (s < len);
                int tout = act ? (dir ? (len - 1 - s) : s) : s;
                float zi = zs[r][j];
                float zj = zs[r][150 + j];
                float zf = zs[r][300 + j];
                float zo = zs[r][450 + j];
                float hn = 0.f;
                if (act) {
                    float cn = c[i] * sigf(zf + 1.0f) + sigf(zi) * tanhf_fast(zj);
                    hn = tanhf_fast(cn) * sigf(zo);
                    c[i]  = cn;
                    hv[i] = hn;
                }
                out[(b * 70 + tout) * 300 + dir * 150 + j] = hn;
            }
            *(float4*)&hT[j][rg2 * 4] = make_float4(hv[0], hv[1], hv[2], hv[3]);
        }
        __syncthreads();
    }
}

// ---------------- head: dense + relu (at t=len-1 only) + logits + argmax ------
__global__ __launch_bounds__(256) void head_kernel(
    const float* __restrict__ seq, const float* __restrict__ dW,
    const float* __restrict__ db, const float* __restrict__ W2,
    const float* __restrict__ b2, float* __restrict__ outp, int out_size) {
    __shared__ float xs[300];
    __shared__ float s0[256], s1[256];
    int b   = blockIdx.x;
    int tid = threadIdx.x;
    int len = g_lens[b];
    int t   = len - 1;   // len >= 1 always
    const float* x = seq + (b * 70 + t) * 300;
    for (int i = tid; i < 300; i += 256) xs[i] = x[i];
    __syncthreads();

    float p0 = 0.f, p1 = 0.f;
    if (tid < 150) {
        float acc = db[tid];
        #pragma unroll 4
        for (int k = 0; k < 300; k++) acc += xs[k] * dW[k * 150 + tid];
        float h = fmaxf(acc, 0.f);
        p0 = h * W2[tid * 2];
        p1 = h * W2[tid * 2 + 1];
    }
    s0[tid] = p0; s1[tid] = p1;
    __syncthreads();
    for (int st = 128; st > 0; st >>= 1) {
        if (tid < st) { s0[tid] += s0[tid + st]; s1[tid] += s1[tid + st]; }
        __syncthreads();
    }
    if (tid == 0) {
        float l0 = s0[0] + b2[0];
        float l1 = s1[0] + b2[1];
        outp[b * 2]     = l0;
        outp[b * 2 + 1] = l1;
        if (out_size >= 3 * B_)               // preds appended after logits
            outp[2 * B_ + b] = (l1 > l0) ? 1.f : 0.f;
    }
}

// ---------------- launch ----------------
extern "C" void kernel_launch(void* const* d_in, const int* in_sizes, int n_in,
                              void* d_out, int out_size) {
    const float* X     = (const float*)d_in[0];
    const int*   Xmask = (const int*)  d_in[1];
    const float* fwk   = (const float*)d_in[2];
    const float* fwb   = (const float*)d_in[3];
    const float* bwk   = (const float*)d_in[4];
    const float* bwb   = (const float*)d_in[5];
    const float* dW    = (const float*)d_in[6];
    const float* db    = (const float*)d_in[7];
    const float* W2    = (const float*)d_in[8];
    const float* b2    = (const float*)d_in[9];

    float *zxf, *zxb, *buf0, *buf1;
    cudaGetSymbolAddress((void**)&zxf,  g_zx_f);
    cudaGetSymbolAddress((void**)&zxb,  g_zx_b);
    cudaGetSymbolAddress((void**)&buf0, g_buf0);
    cudaGetSymbolAddress((void**)&buf1, g_buf1);

    lens_kernel<<<2, 512>>>(Xmask);

    dim3 gemm_grid(M_ / 128, (600 + 63) / 64);   // (560, 10)
    const float* in   = X;
    float*       outb = buf0;
    for (int L = 0; L < DEPTH_; L++) {
        const float* kf = fwk + (size_t)L * 450 * 600;
        const float* kb = bwk + (size_t)L * 450 * 600;
        sgemm_bias<<<gemm_grid, 256>>>(in, kf, fwb + L * 600, zxf);
        sgemm_bias<<<gemm_grid, 256>>>(in, kb, bwb + L * 600, zxb);
        lstm_layer<<<dim3(B_ / 16, 2), 608>>>(zxf, zxb,
                                              kf + 300 * 600, kb + 300 * 600,
                                              outb);
        in   = outb;
        outb = (outb == buf0) ? buf1 : buf0;
    }
    head_kernel<<<B_, 256>>>(in, dW, db, W2, b2, (float*)d_out, out_size);
}

// round 2
// speedup vs baseline: 1.0017x; 1.0017x over previous
#include <cuda_runtime.h>
#include <cuda_bf16.h>
#include <math.h>

// Problem constants
#define B_    1024
#define T_    70
#define E_    300     // input dim per layer (= 2H)
#define H_    150
#define G_    600     // 4H gate width
#define DEPTH_ 5
#define M_    (B_ * T_)   // 71680 rows for the big input GEMM

// ---------------- scratch (static device memory; no allocation) ----------------
__device__ float g_zx_f[M_ * G_];   // forward  input pre-activations  [B*T, 600]
__device__ float g_zx_b[M_ * G_];   // backward input pre-activations  [B*T, 600]
__device__ float g_buf0[M_ * E_];   // layer ping buffer [B,T,300]
__device__ float g_buf1[M_ * E_];   // layer pong buffer
__device__ int   g_lens[B_];

// ---------------- helpers ----------------
__device__ __forceinline__ float sigf(float x) {
    return __fdividef(1.f, 1.f + __expf(-x));
}
__device__ __forceinline__ float tanhf_fast(float x) {
    // tanh(x) = 2*sigmoid(2x) - 1 ; saturates correctly for large |x|
    return __fdividef(2.f, 1.f + __expf(-2.f * x)) - 1.f;
}

// ---------------- lens = sum(mask) per batch row ----------------
__global__ void lens_kernel(const int* __restrict__ mask) {
    int b = blockIdx.x * blockDim.x + threadIdx.x;
    if (b < B_) {
        int s = 0;
        #pragma unroll
        for (int t = 0; t < T_; t++) s += mask[b * T_ + t];
        g_lens[b] = s;
    }
}

// ---------------- SGEMM: C[M,600] = A[M,300] @ Wk[300,600] + bias ----------------
// Tiles: BM=128, BN=64, BK=16; 256 threads; 8x4 per-thread tile.
__global__ __launch_bounds__(256) void sgemm_bias(
    const float* __restrict__ A, const float* __restrict__ Wk,
    const float* __restrict__ bias, float* __restrict__ C) {
    __shared__ float As[16][132];   // As[k][m], padded
    __shared__ float Ws[16][68];    // Ws[k][n], padded

    const int tid = threadIdx.x;
    const int m0 = blockIdx.x * 128;
    const int n0 = blockIdx.y * 64;
    const int tx = tid & 15;        // 4-col group
    const int ty = tid >> 4;        // 8-row group

    float acc[8][4];
    #pragma unroll
    for (int i = 0; i < 8; i++)
        #pragma unroll
        for (int j = 0; j < 4; j++) acc[i][j] = 0.f;

    for (int k0 = 0; k0 < 300; k0 += 16) {
        // load A tile (128x16) as 512 float4s, 2 per thread, store transposed
        #pragma unroll
        for (int l = 0; l < 2; l++) {
            int q   = tid + l * 256;
            int row = q >> 2;
            int kq  = (q & 3) * 4;
            float4 v = make_float4(0.f, 0.f, 0.f, 0.f);
            if (k0 + kq < 300)      // K=300 is a multiple of 4: quad all-or-none
                v = *(const float4*)(A + (m0 + row) * 300 + k0 + kq);
            As[kq + 0][row] = v.x;
            As[kq + 1][row] = v.y;
            As[kq + 2][row] = v.z;
            As[kq + 3][row] = v.w;
        }
        // load W tile (16x64) as 256 float4s, 1 per thread
        {
            int kk = tid >> 4;
            int nq = (tid & 15) * 4;
            int gn = n0 + nq;
            float4 v = make_float4(0.f, 0.f, 0.f, 0.f);
            if ((k0 + kk) < 300 && gn < 600)   // N=600 mult of 4: all-or-none
                v = *(const float4*)(Wk + (k0 + kk) * 600 + gn);
            *(float4*)&Ws[kk][nq] = v;
        }
        __syncthreads();

        #pragma unroll
        for (int kk = 0; kk < 16; kk++) {
            float4 a0 = *(const float4*)&As[kk][ty * 8];
            float4 a1 = *(const float4*)&As[kk][ty * 8 + 4];
            float4 w  = *(const float4*)&Ws[kk][tx * 4];
            float ar[8] = {a0.x, a0.y, a0.z, a0.w, a1.x, a1.y, a1.z, a1.w};
            float wr[4] = {w.x, w.y, w.z, w.w};
            #pragma unroll
            for (int i = 0; i < 8; i++)
                #pragma unroll
                for (int j = 0; j < 4; j++)
                    acc[i][j] += ar[i] * wr[j];
        }
        __syncthreads();
    }

    int gn = n0 + tx * 4;
    if (gn < 600) {
        float4 bv = *(const float4*)(bias + gn);
        #pragma unroll
        for (int i = 0; i < 8; i++) {
            int gm = m0 + ty * 8 + i;
            float4 o = make_float4(acc[i][0] + bv.x, acc[i][1] + bv.y,
                                   acc[i][2] + bv.z, acc[i][3] + bv.w);
            *(float4*)(C + gm * 600 + gn) = o;
        }
    }
}

// ---------------- recurrent layer (fw + bw in one grid) ----------------
// Block: 16 batch rows, 608 threads. Persistent over all 70 timesteps.
// Phase 1: z[16,600] = Zx[b,t] + h[16,150] @ Wh[150,600] (Wh streamed from L2)
// Phase 2: gates -> c,h update; h kept in SMEM (hT[k][r] layout), c in registers.
// Backward direction scans t = len-1-s per row; inactive steps write zeros at t=s.
__global__ __launch_bounds__(608) void lstm_layer(
    const float* __restrict__ zx_f, const float* __restrict__ zx_b,
    const float* __restrict__ wh_f, const float* __restrict__ wh_b,
    float* __restrict__ out) {
    __shared__ float hT[150][16];     // hT[k][r]
    __shared__ float zs[16][600];     // z staging
    __shared__ int   lens_s[16];

    const int tid = threadIdx.x;
    const int dir = blockIdx.y;
    const int b0  = blockIdx.x * 16;
    const float* zx = dir ? zx_b : zx_f;
    const float* Wh = dir ? wh_b : wh_f;

    if (tid < 16) lens_s[tid] = g_lens[b0 + tid];
    for (int i = tid; i < 150 * 16; i += 608) ((float*)hT)[i] = 0.f;

    // phase-1 mapping: 600 threads = 150 col-groups x 4 row-groups (4 cols x 4 rows each)
    const int cg  = (tid < 600) ? (tid % 150) : 0;
    const int rg1 = (tid < 600) ? (tid / 150) : 0;
    // phase-2 mapping: 600 threads = hidden j (0..149) x 4 row-groups
    const int j   = tid % 150;
    const int rg2 = tid / 150;

    float c[4] = {0.f, 0.f, 0.f, 0.f};
    __syncthreads();

    for (int s = 0; s < T_; s++) {
        // ---- phase 1: GEMM ----
        if (tid < 600) {
            float a[4][4];
            #pragma unroll
            for (int i = 0; i < 4; i++) {
                int r   = rg1 * 4 + i;
                int b   = b0 + r;
                int len = lens_s[r];
                bool act = (s < len);
                int t = act ? (dir ? (len - 1 - s) : s) : 0;
                float4 z4 = *(const float4*)(zx + (b * 70 + t) * 600 + cg * 4);
                a[i][0] = z4.x; a[i][1] = z4.y; a[i][2] = z4.z; a[i][3] = z4.w;
            }
            const float*  wp = Wh + cg * 4;
            const float4* hp = ((const float4*)hT) + rg1;   // hT row = 4 float4s
            #pragma unroll 5
            for (int k = 0; k < 150; k++) {
                float4 w = *(const float4*)(wp + k * 600);
                float4 h = hp[k * 4];
                float hh[4] = {h.x, h.y, h.z, h.w};
                float ww[4] = {w.x, w.y, w.z, w.w};
                #pragma unroll
                for (int i = 0; i < 4; i++)
                    #pragma unroll
                    for (int q = 0; q < 4; q++)
                        a[i][q] += hh[i] * ww[q];
            }
            #pragma unroll
            for (int i = 0; i < 4; i++)
                *(float4*)&zs[rg1 * 4 + i][cg * 4] =
                    make_float4(a[i][0], a[i][1], a[i][2], a[i][3]);
        }
        __syncthreads();

        // ---- phase 2: gates + state update ----
        if (tid < 600) {
            float4 hold = *(float4*)&hT[j][rg2 * 4];
            float hv[4] = {hold.x, hold.y, hold.z, hold.w};
            #pragma unroll
            for (int i = 0; i < 4; i++) {
                int r   = rg2 * 4 + i;
                int b   = b0 + r;
                int len = lens_s[r];
                bool act = (s < len);
                int tout = act ? (dir ? (len - 1 - s) : s) : s;
                float zi = zs[r][j];
                float zj = zs[r][150 + j];
                float zf = zs[r][300 + j];
                float zo = zs[r][450 + j];
                float hn = 0.f;
                if (act) {
                    float cn = c[i] * sigf(zf + 1.0f) + sigf(zi) * tanhf_fast(zj);
                    hn = tanhf_fast(cn) * sigf(zo);
                    c[i]  = cn;
                    hv[i] = hn;
                }
                out[(b * 70 + tout) * 300 + dir * 150 + j] = hn;
            }
            *(float4*)&hT[j][rg2 * 4] = make_float4(hv[0], hv[1], hv[2], hv[3]);
        }
        __syncthreads();
    }
}

// ---------------- head: dense + relu (at t=len-1 only) + logits + argmax ------
__global__ __launch_bounds__(256) void head_kernel(
    const float* __restrict__ seq, const float* __restrict__ dW,
    const float* __restrict__ db, const float* __restrict__ W2,
    const float* __restrict__ b2, float* __restrict__ outp, int out_size) {
    __shared__ float xs[300];
    __shared__ float s0[256], s1[256];
    int b   = blockIdx.x;
    int tid = threadIdx.x;
    int len = g_lens[b];
    int t   = len - 1;   // len >= 1 always
    const float* x = seq + (b * 70 + t) * 300;
    for (int i = tid; i < 300; i += 256) xs[i] = x[i];
    __syncthreads();

    float p0 = 0.f, p1 = 0.f;
    if (tid < 150) {
        float acc = db[tid];
        #pragma unroll 4
        for (int k = 0; k < 300; k++) acc += xs[k] * dW[k * 150 + tid];
        float h = fmaxf(acc, 0.f);
        p0 = h * W2[tid * 2];
        p1 = h * W2[tid * 2 + 1];
    }
    s0[tid] = p0; s1[tid] = p1;
    __syncthreads();
    for (int st = 128; st > 0; st >>= 1) {
        if (tid < st) { s0[tid] += s0[tid + st]; s1[tid] += s1[tid + st]; }
        __syncthreads();
    }
    if (tid == 0) {
        float l0 = s0[0] + b2[0];
        float l1 = s1[0] + b2[1];
        outp[b * 2]     = l0;
        outp[b * 2 + 1] = l1;
        if (out_size >= 3 * B_)               // preds appended after logits
            outp[2 * B_ + b] = (l1 > l0) ? 1.f : 0.f;
    }
}

// ---------------- launch ----------------
extern "C" void kernel_launch(void* const* d_in, const int* in_sizes, int n_in,
                              void* d_out, int out_size) {
    const float* X     = (const float*)d_in[0];
    const int*   Xmask = (const int*)  d_in[1];
    const float* fwk   = (const float*)d_in[2];
    const float* fwb   = (const float*)d_in[3];
    const float* bwk   = (const float*)d_in[4];
    const float* bwb   = (const float*)d_in[5];
    const float* dW    = (const float*)d_in[6];
    const float* db    = (const float*)d_in[7];
    const float* W2    = (const float*)d_in[8];
    const float* b2    = (const float*)d_in[9];

    float *zxf, *zxb, *buf0, *buf1;
    cudaGetSymbolAddress((void**)&zxf,  g_zx_f);
    cudaGetSymbolAddress((void**)&zxb,  g_zx_b);
    cudaGetSymbolAddress((void**)&buf0, g_buf0);
    cudaGetSymbolAddress((void**)&buf1, g_buf1);

    lens_kernel<<<2, 512>>>(Xmask);

    dim3 gemm_grid(M_ / 128, (600 + 63) / 64);   // (560, 10)
    const float* in   = X;
    float*       outb = buf0;
    for (int L = 0; L < DEPTH_; L++) {
        const float* kf = fwk + (size_t)L * 450 * 600;
        const float* kb = bwk + (size_t)L * 450 * 600;
        sgemm_bias<<<gemm_grid, 256>>>(in, kf, fwb + L * 600, zxf);
        sgemm_bias<<<gemm_grid, 256>>>(in, kb, bwb + L * 600, zxb);
        lstm_layer<<<dim3(B_ / 16, 2), 608>>>(zxf, zxb,
                                              kf + 300 * 600, kb + 300 * 600,
                                              outb);
        in   = outb;
        outb = (outb == buf0) ? buf1 : buf0;
    }
    head_kernel<<<B_, 256>>>(in, dW, db, W2, b2, (float*)d_out, out_size);
}